// round 9
// baseline (speedup 1.0000x reference)
#include <cuda_runtime.h>
#include <cstdint>
#include <math.h>

#define HIDDEN 1024
#define HEADS  16
#define HD     64
#define SEQ    2048
#define BATCH  4
#define M_TOT  (BATCH*SEQ)   // 8192

// ---------------- scratch (device globals: allocation-free) ----------------
__device__ float g_q[(size_t)M_TOT * HIDDEN];
__device__ float g_k[(size_t)M_TOT * HIDDEN];
__device__ float g_v[(size_t)M_TOT * HIDDEN];
__device__ float g_attn[(size_t)M_TOT * HIDDEN];
__device__ int   g_bflag[(SEQ/128) * (SEQ/64)];

// ---------------------------------------------------------------------------
// helpers
// ---------------------------------------------------------------------------
__device__ __forceinline__ unsigned f2tf(float x) {
    unsigned r;
    asm("cvt.rna.tf32.f32 %0, %1;" : "=r"(r) : "f"(x));
    return r;
}

__device__ __forceinline__ void mma_tf32(float* c,
    unsigned a0, unsigned a1, unsigned a2, unsigned a3,
    unsigned b0, unsigned b1)
{
    asm volatile(
        "mma.sync.aligned.m16n8k8.row.col.f32.tf32.tf32.f32 "
        "{%0,%1,%2,%3}, {%4,%5,%6,%7}, {%8,%9}, {%0,%1,%2,%3};\n"
        : "+f"(c[0]), "+f"(c[1]), "+f"(c[2]), "+f"(c[3])
        : "r"(a0), "r"(a1), "r"(a2), "r"(a3), "r"(b0), "r"(b1));
}

__device__ __forceinline__ void ldsm_x4(unsigned* r, uint32_t addr) {
    asm volatile(
        "ldmatrix.sync.aligned.m8n8.x4.shared.b16 {%0,%1,%2,%3}, [%4];"
        : "=r"(r[0]), "=r"(r[1]), "=r"(r[2]), "=r"(r[3])
        : "r"(addr));
}

__device__ __forceinline__ uint32_t smem_u32(const void* p) {
    uint32_t a;
    asm("{ .reg .u64 t; cvta.to.shared.u64 t, %1; cvt.u32.u64 %0, t; }"
        : "=r"(a) : "l"(p));
    return a;
}

// ---------------------------------------------------------------------------
// bias tile flags: flag[qt*32+kt] = any nonzero in 128x64 bias tile
// ---------------------------------------------------------------------------
__global__ __launch_bounds__(256) void bias_flags(const float* __restrict__ bias,
                                                  int* __restrict__ flags)
{
    const int qt = blockIdx.x >> 5;
    const int kt = blockIdx.x & 31;
    const int tid = threadIdx.x;
    bool nz = false;
    #pragma unroll
    for (int r = 0; r < 8; r++) {
        int f   = tid + r * 256;
        int row = f >> 4;
        int cq  = (f & 15) << 2;
        float4 v = *(const float4*)(bias + (size_t)(qt * 128 + row) * SEQ + kt * 64 + cq);
        nz |= (v.x != 0.f) | (v.y != 0.f) | (v.z != 0.f) | (v.w != 0.f);
    }
    int any = __syncthreads_or((int)nz);
    if (tid == 0) flags[blockIdx.x] = any;
}

// ---------------------------------------------------------------------------
// tf32 GEMM: C = scale * (A @ W^T + bias). CTA tile 128m x 256n x 32k,
// 8 warps (2m x 4n), warp tile 64x64 -> 8 LDSM feed 32 MMAs per kt.
// Double-buffered smem, ldmatrix fragments, register prefetch.
// ---------------------------------------------------------------------------
#define GK 1024
#define ASTR 36
#define GSA (128*ASTR)        // A words per stage
#define GSW (256*ASTR)        // W words per stage
#define GEMM_SMEM ((2*GSA + 2*GSW) * 4)   // 110592 B

__global__ __launch_bounds__(256, 1) void gemm_tf32(
    const float* __restrict__ A, const float* __restrict__ W,
    const float* __restrict__ bias, float* __restrict__ C, float scale)
{
    extern __shared__ unsigned gsm[];
    unsigned* As = gsm;               // [2][128][ASTR]
    unsigned* Ws = gsm + 2 * GSA;     // [2][256][ASTR]
    const uint32_t sbA = smem_u32(As);
    const uint32_t sbW = smem_u32(Ws);

    const int tid  = threadIdx.x;
    const int lane = tid & 31;
    const int warp = tid >> 5;
    const int g    = lane >> 2;
    const int tig  = lane & 3;
    const int wm   = (warp >> 2) * 64;    // 2 m-groups
    const int wn   = (warp & 3) * 64;     // 4 n-groups of 64
    const int m0   = blockIdx.y * 128;
    const int n0   = blockIdx.x * 256;

    const float* Ag = A + (size_t)m0 * GK;
    const float* Wg = W + (size_t)n0 * GK;

    const int srow = tid >> 3;        // 0..31
    const int skq  = (tid & 7) << 2;  // 0..28

    const int rA = (lane & 7) + ((lane >> 3) & 1) * 8;
    const int cA = (lane >> 4) * 4;
    const uint32_t aoff = (uint32_t)(((wm + rA) * ASTR + cA) * 4);
    const int rB = (lane & 7) + (lane >> 4) * 8;
    const int cB = ((lane >> 3) & 1) * 4;
    const uint32_t boff = (uint32_t)(((wn + rB) * ASTR + cB) * 4);

    float acc[4][8][4];
    #pragma unroll
    for (int i = 0; i < 4; i++)
        #pragma unroll
        for (int j = 0; j < 8; j++)
            #pragma unroll
            for (int e = 0; e < 4; e++) acc[i][j][e] = 0.f;

    float4 pa[4], pw[8];
    #pragma unroll
    for (int r = 0; r < 4; r++)
        pa[r] = *(const float4*)(Ag + (size_t)(srow + 32 * r) * GK + skq);
    #pragma unroll
    for (int r = 0; r < 8; r++)
        pw[r] = *(const float4*)(Wg + (size_t)(srow + 32 * r) * GK + skq);

    #pragma unroll
    for (int r = 0; r < 4; r++) {
        int row = srow + 32 * r;
        *(uint4*)&As[row * ASTR + skq] =
            make_uint4(f2tf(pa[r].x), f2tf(pa[r].y), f2tf(pa[r].z), f2tf(pa[r].w));
    }
    #pragma unroll
    for (int r = 0; r < 8; r++) {
        int row = srow + 32 * r;
        *(uint4*)&Ws[row * ASTR + skq] =
            make_uint4(f2tf(pw[r].x), f2tf(pw[r].y), f2tf(pw[r].z), f2tf(pw[r].w));
    }
    __syncthreads();

    for (int k0 = 0; k0 < GK; k0 += 32) {
        const int cur = (k0 >> 5) & 1;
        const int nxt = cur ^ 1;
        const bool more = (k0 + 32 < GK);

        if (more) {
            #pragma unroll
            for (int r = 0; r < 4; r++)
                pa[r] = *(const float4*)(Ag + (size_t)(srow + 32 * r) * GK + k0 + 32 + skq);
            #pragma unroll
            for (int r = 0; r < 8; r++)
                pw[r] = *(const float4*)(Wg + (size_t)(srow + 32 * r) * GK + k0 + 32 + skq);
        }

        const uint32_t aStage = sbA + (uint32_t)(cur * GSA * 4) + aoff;
        const uint32_t wStage = sbW + (uint32_t)(cur * GSW * 4) + boff;
        #pragma unroll
        for (int kt = 0; kt < 4; kt++) {
            const uint32_t kbB = (uint32_t)(kt * 8 * 4);
            unsigned af[4][4], bf[4][4];
            #pragma unroll
            for (int mt = 0; mt < 4; mt++)
                ldsm_x4(af[mt], aStage + (uint32_t)(mt * 16 * ASTR * 4) + kbB);
            #pragma unroll
            for (int p = 0; p < 4; p++)
                ldsm_x4(bf[p], wStage + (uint32_t)(p * 16 * ASTR * 4) + kbB);
            #pragma unroll
            for (int mt = 0; mt < 4; mt++) {
                #pragma unroll
                for (int p = 0; p < 4; p++) {
                    mma_tf32(acc[mt][2*p],   af[mt][0], af[mt][1], af[mt][2], af[mt][3],
                             bf[p][0], bf[p][1]);
                    mma_tf32(acc[mt][2*p+1], af[mt][0], af[mt][1], af[mt][2], af[mt][3],
                             bf[p][2], bf[p][3]);
                }
            }
        }

        if (more) {
            #pragma unroll
            for (int r = 0; r < 4; r++) {
                int row = nxt * GSA + (srow + 32 * r) * ASTR + skq;
                *(uint4*)&As[row] =
                    make_uint4(f2tf(pa[r].x), f2tf(pa[r].y), f2tf(pa[r].z), f2tf(pa[r].w));
            }
            #pragma unroll
            for (int r = 0; r < 8; r++) {
                int row = nxt * GSW + (srow + 32 * r) * ASTR + skq;
                *(uint4*)&Ws[row] =
                    make_uint4(f2tf(pw[r].x), f2tf(pw[r].y), f2tf(pw[r].z), f2tf(pw[r].w));
            }
        }
        __syncthreads();
    }

    #pragma unroll
    for (int mt = 0; mt < 4; mt++) {
        #pragma unroll
        for (int nt = 0; nt < 8; nt++) {
            int ncol = n0 + wn + nt * 8 + 2 * tig;
            float2 bv = *(const float2*)(bias + ncol);
            int r0 = m0 + wm + mt * 16 + g;
            *(float2*)(C + (size_t)r0 * HIDDEN + ncol) =
                make_float2(scale * (acc[mt][nt][0] + bv.x), scale * (acc[mt][nt][1] + bv.y));
            *(float2*)(C + (size_t)(r0 + 8) * HIDDEN + ncol) =
                make_float2(scale * (acc[mt][nt][2] + bv.x), scale * (acc[mt][nt][3] + bv.y));
        }
    }
}

// ---------------------------------------------------------------------------
// Flash attention (unchanged from R6): tf32 mma + ldmatrix, single-buffered
// K/V, 2 CTAs/SM, register prefetch, two syncs per 64-key chunk.
// ---------------------------------------------------------------------------
#define QSS 68
#define VSS 72
#define ATTN_SMEM ((128*QSS + 128*QSS + 64*QSS + 64*VSS) * 4)   // 105472 B

__global__ __launch_bounds__(256, 2) void attn_tf32(
    const float* __restrict__ Q, const float* __restrict__ K,
    const float* __restrict__ V, const float* __restrict__ bias,
    const int* __restrict__ flags, float* __restrict__ O)
{
    extern __shared__ unsigned sm[];
    unsigned* Qs = sm;
    unsigned* Ps = Qs + 128 * QSS;
    unsigned* Ks = Ps + 128 * QSS;
    unsigned* Vs = Ks + 64 * QSS;
    const uint32_t sbQ = smem_u32(Qs);
    const uint32_t sbP = smem_u32(Ps);
    const uint32_t sbK = smem_u32(Ks);

    const int tid  = threadIdx.x;
    const int lane = tid & 31;
    const int warp = tid >> 5;
    const int g    = lane >> 2;
    const int tig  = lane & 3;
    const int q0   = blockIdx.x * 128;
    const int h    = blockIdx.y;
    const int b    = blockIdx.z;
    const size_t base = (size_t)b * SEQ * HIDDEN + (size_t)h * HD;
    const int qb   = warp * 16;

    const int srow = tid >> 4;
    const int sdq  = (tid & 15) << 2;

    const int rA = (lane & 7) + ((lane >> 3) & 1) * 8;
    const int cA = (lane >> 4) * 4;
    const uint32_t qAddr0 = sbQ + (uint32_t)(((qb + rA) * QSS + cA) * 4);
    const uint32_t pAddr0 = sbP + (uint32_t)(((qb + rA) * QSS + cA) * 4);
    const int rB = (lane & 7) + (lane >> 4) * 8;
    const int cB = ((lane >> 3) & 1) * 4;
    const uint32_t kAddr0 = sbK + (uint32_t)((rB * QSS + cB) * 4);

    #pragma unroll
    for (int r = 0; r < 8; r++) {
        int row = srow + 16 * r;
        float4 v = *(const float4*)(Q + base + (size_t)(q0 + row) * HIDDEN + sdq);
        *(uint4*)&Qs[row * QSS + sdq] =
            make_uint4(f2tf(v.x), f2tf(v.y), f2tf(v.z), f2tf(v.w));
    }

    float4 pk[4], pv4[4];
    #pragma unroll
    for (int r = 0; r < 4; r++) {
        int row = srow + 16 * r;
        pk[r]  = *(const float4*)(K + base + (size_t)row * HIDDEN + sdq);
        pv4[r] = *(const float4*)(V + base + (size_t)row * HIDDEN + sdq);
    }
    #pragma unroll
    for (int r = 0; r < 4; r++) {
        int row = srow + 16 * r;
        *(uint4*)&Ks[row * QSS + sdq] =
            make_uint4(f2tf(pk[r].x), f2tf(pk[r].y), f2tf(pk[r].z), f2tf(pk[r].w));
        *(uint4*)&Vs[row * VSS + sdq] =
            make_uint4(f2tf(pv4[r].x), f2tf(pv4[r].y), f2tf(pv4[r].z), f2tf(pv4[r].w));
    }
    __syncthreads();

    float o[8][4];
    float mr[2], lr[2];
    mr[0] = mr[1] = -1e30f;
    lr[0] = lr[1] = 0.f;
    #pragma unroll
    for (int nt = 0; nt < 8; nt++)
        #pragma unroll
        for (int e = 0; e < 4; e++) o[nt][e] = 0.f;

    const int qr = qb + g;

    for (int c = 0; c < SEQ / 64; c++) {
        const bool more = (c + 1 < SEQ / 64);

        if (more) {
            const int k1 = (c + 1) * 64;
            #pragma unroll
            for (int r = 0; r < 4; r++) {
                int row = srow + 16 * r;
                pk[r]  = *(const float4*)(K + base + (size_t)(k1 + row) * HIDDEN + sdq);
                pv4[r] = *(const float4*)(V + base + (size_t)(k1 + row) * HIDDEN + sdq);
            }
        }

        float s[8][4];
        #pragma unroll
        for (int nt = 0; nt < 8; nt++)
            #pragma unroll
            for (int e = 0; e < 4; e++) s[nt][e] = 0.f;

        #pragma unroll
        for (int kt = 0; kt < 8; kt++) {
            const uint32_t kbB = (uint32_t)(kt * 8 * 4);
            unsigned qf[4], kf[4][4];
            ldsm_x4(qf, qAddr0 + kbB);
            #pragma unroll
            for (int p = 0; p < 4; p++)
                ldsm_x4(kf[p], kAddr0 + (uint32_t)(p * 16 * QSS * 4) + kbB);
            #pragma unroll
            for (int p = 0; p < 4; p++) {
                mma_tf32(s[2*p],   qf[0], qf[1], qf[2], qf[3], kf[p][0], kf[p][1]);
                mma_tf32(s[2*p+1], qf[0], qf[1], qf[2], qf[3], kf[p][2], kf[p][3]);
            }
        }

        if (flags[blockIdx.x * (SEQ / 64) + c]) {
            const int k0 = c * 64;
            int r0 = q0 + qr;
            #pragma unroll
            for (int nt = 0; nt < 8; nt++) {
                int col = k0 + nt * 8 + 2 * tig;
                float2 b0 = *(const float2*)(bias + (size_t)r0 * SEQ + col);
                s[nt][0] += b0.x; s[nt][1] += b0.y;
                float2 b1 = *(const float2*)(bias + (size_t)(r0 + 8) * SEQ + col);
                s[nt][2] += b1.x; s[nt][3] += b1.y;
            }
        }

        #pragma unroll
        for (int h2 = 0; h2 < 2; h2++) {
            float mx = -1e30f;
            #pragma unroll
            for (int nt = 0; nt < 8; nt++)
                mx = fmaxf(mx, fmaxf(s[nt][2 * h2], s[nt][2 * h2 + 1]));
            mx = fmaxf(mx, __shfl_xor_sync(0xffffffffu, mx, 1));
            mx = fmaxf(mx, __shfl_xor_sync(0xffffffffu, mx, 2));
            float mn = fmaxf(mr[h2], mx);
            float al = __expf(mr[h2] - mn);
            mr[h2] = mn;
            float sum = 0.f;
            #pragma unroll
            for (int nt = 0; nt < 8; nt++) {
                float p0 = __expf(s[nt][2 * h2]     - mn);
                float p1 = __expf(s[nt][2 * h2 + 1] - mn);
                s[nt][2 * h2] = p0;  s[nt][2 * h2 + 1] = p1;
                sum += p0 + p1;
            }
            sum += __shfl_xor_sync(0xffffffffu, sum, 1);
            sum += __shfl_xor_sync(0xffffffffu, sum, 2);
            lr[h2] = lr[h2] * al + sum;
            #pragma unroll
            for (int nt = 0; nt < 8; nt++) {
                o[nt][2 * h2]     *= al;
                o[nt][2 * h2 + 1] *= al;
            }
        }

        #pragma unroll
        for (int nt = 0; nt < 8; nt++) {
            int col = nt * 8 + 2 * tig;
            *(uint2*)&Ps[qr * QSS + col] =
                make_uint2(f2tf(s[nt][0]), f2tf(s[nt][1]));
            *(uint2*)&Ps[(qr + 8) * QSS + col] =
                make_uint2(f2tf(s[nt][2]), f2tf(s[nt][3]));
        }
        __syncwarp();

        #pragma unroll
        for (int kt = 0; kt < 8; kt++) {
            const int kb = kt * 8;
            unsigned pf[4];
            ldsm_x4(pf, pAddr0 + (uint32_t)(kb * 4));
            #pragma unroll
            for (int nt = 0; nt < 8; nt++) {
                const unsigned* vp = Vs + (kb + tig) * VSS + nt * 8 + g;
                mma_tf32(o[nt], pf[0], pf[1], pf[2], pf[3], vp[0], vp[4 * VSS]);
            }
        }

        if (more) {
            __syncthreads();
            #pragma unroll
            for (int r = 0; r < 4; r++) {
                int row = srow + 16 * r;
                *(uint4*)&Ks[row * QSS + sdq] =
                    make_uint4(f2tf(pk[r].x), f2tf(pk[r].y), f2tf(pk[r].z), f2tf(pk[r].w));
                *(uint4*)&Vs[row * VSS + sdq] =
                    make_uint4(f2tf(pv4[r].x), f2tf(pv4[r].y), f2tf(pv4[r].z), f2tf(pv4[r].w));
            }
            __syncthreads();
        }
    }

    float inv0 = 1.f / lr[0];
    float inv1 = 1.f / lr[1];
    int r0 = q0 + qr;
    #pragma unroll
    for (int nt = 0; nt < 8; nt++) {
        int col = h * HD + nt * 8 + 2 * tig;
        *(float2*)(O + (size_t)b * SEQ * HIDDEN + (size_t)r0 * HIDDEN + col) =
            make_float2(o[nt][0] * inv0, o[nt][1] * inv0);
        *(float2*)(O + (size_t)b * SEQ * HIDDEN + (size_t)(r0 + 8) * HIDDEN + col) =
            make_float2(o[nt][2] * inv1, o[nt][3] * inv1);
    }
}

// ---------------------------------------------------------------------------
extern "C" void kernel_launch(void* const* d_in, const int* in_sizes, int n_in,
                              void* d_out, int out_size)
{
    (void)in_sizes; (void)n_in; (void)out_size;
    const float* query = (const float*)d_in[0];
    const float* bias  = (const float*)d_in[1];
    const float* wq    = (const float*)d_in[2];
    const float* bq    = (const float*)d_in[3];
    const float* wk    = (const float*)d_in[4];
    const float* bk    = (const float*)d_in[5];
    const float* wv    = (const float*)d_in[6];
    const float* bv    = (const float*)d_in[7];
    const float* wo    = (const float*)d_in[8];
    const float* bo    = (const float*)d_in[9];
    float* out = (float*)d_out;

    float *qb, *kb, *vb, *ab;
    int* bfl;
    cudaGetSymbolAddress((void**)&qb, g_q);
    cudaGetSymbolAddress((void**)&kb, g_k);
    cudaGetSymbolAddress((void**)&vb, g_v);
    cudaGetSymbolAddress((void**)&ab, g_attn);
    cudaGetSymbolAddress((void**)&bfl, g_bflag);

    cudaFuncSetAttribute(gemm_tf32,
                         cudaFuncAttributeMaxDynamicSharedMemorySize, GEMM_SMEM);
    cudaFuncSetAttribute(attn_tf32,
                         cudaFuncAttributeMaxDynamicSharedMemorySize, ATTN_SMEM);

    bias_flags<<<(SEQ/128) * (SEQ/64), 256>>>(bias, bfl);

    dim3 ggrid(HIDDEN / 256, M_TOT / 128);   // (4, 64)
    const float qscale = 0.125f;             // 64^-0.5

    gemm_tf32<<<ggrid, 256, GEMM_SMEM>>>(query, wq, bq, qb, qscale);
    gemm_tf32<<<ggrid, 256, GEMM_SMEM>>>(query, wk, bk, kb, 1.0f);
    gemm_tf32<<<ggrid, 256, GEMM_SMEM>>>(query, wv, bv, vb, 1.0f);

    dim3 agrid(SEQ / 128, HEADS, BATCH);     // (16, 16, 4)
    attn_tf32<<<agrid, 256, ATTN_SMEM>>>(qb, kb, vb, bias, bfl, ab);

    gemm_tf32<<<ggrid, 256, GEMM_SMEM>>>(ab, wo, bo, out, 1.0f);
}